// round 14
// baseline (speedup 1.0000x reference)
#include <cuda_runtime.h>
#include <float.h>

// Problem constants (fixed by the reference: B=16, N=1024, M=21, D=256, V=16)
#define BN_TOTAL (16 * 1024)
#define MPTS 21
#define PP 20      // M-1 points per polyline
#define D1 128
#define D2 256

typedef unsigned long long ull;

// ---- packed f32x2 helpers (Blackwell FFMA2) ----
__device__ __forceinline__ ull pack2(float x, float y) {
    ull r;
    asm("mov.b64 %0, {%1, %2};" : "=l"(r) : "f"(x), "f"(y));
    return r;
}
__device__ __forceinline__ void unpack2(ull v, float& x, float& y) {
    asm("mov.b64 {%0, %1}, %2;" : "=f"(x), "=f"(y) : "l"(v));
}
__device__ __forceinline__ ull ffma2(ull a, ull b, ull c) {
    ull d;
    asm("fma.rn.f32x2 %0, %1, %2, %3;" : "=l"(d) : "l"(a), "l"(b), "l"(c));
    return d;
}

__device__ float g_W23[D1 * D2];   // W2 @ W3[:256]  (128x256)
__device__ float g_bc[D2];         // b2 @ W3[:256] + b3
__device__ float g_scale[D2];      // sine arg multiplier per channel
__device__ int   g_count;
__device__ int   g_active[BN_TOTAL];

// ---- precompute: W23, bc, sine scale table, zero active-count ----
// Grid 129: blocks 0..127 -> one W23 row each (8-way-MLP inner loop);
// block 128 -> bc + scale table + count reset.
__global__ void precompute_w23_kernel(const float* __restrict__ W2,
                                      const float* __restrict__ W3,
                                      const float* __restrict__ b2,
                                      const float* __restrict__ b3) {
    __shared__ float row[D2];
    const int blk = blockIdx.x;
    const int d = threadIdx.x;   // 0..255
    if (blk < 128) {
        row[d] = W2[blk * D2 + d];     // W2 row `blk`
        __syncthreads();
        float acc[8];
        #pragma unroll
        for (int j = 0; j < 8; ++j) acc[j] = 0.f;
        #pragma unroll 1
        for (int k0 = 0; k0 < D2; k0 += 8) {
            #pragma unroll
            for (int j = 0; j < 8; ++j)
                acc[j] = fmaf(row[k0 + j], W3[(k0 + j) * D2 + d], acc[j]);
        }
        float s = ((acc[0] + acc[1]) + (acc[2] + acc[3]))
                + ((acc[4] + acc[5]) + (acc[6] + acc[7]));
        g_W23[blk * D2 + d] = s;
    } else {
        row[d] = b2[d];
        __syncthreads();
        float acc[8];
        #pragma unroll
        for (int j = 0; j < 8; ++j) acc[j] = 0.f;
        #pragma unroll 1
        for (int k0 = 0; k0 < D2; k0 += 8) {
            #pragma unroll
            for (int j = 0; j < 8; ++j)
                acc[j] = fmaf(row[k0 + j], W3[(k0 + j) * D2 + d], acc[j]);
        }
        float s = ((acc[0] + acc[1]) + (acc[2] + acc[3]))
                + ((acc[4] + acc[5]) + (acc[6] + acc[7]));
        g_bc[d] = s + b3[d];
        int i = (d & 127) >> 1;
        float freq = powf(10000.0f, (float)i * (1.0f / 64.0f));
        g_scale[d] = 6.283185307179586f / freq;
        if (d == 0) g_count = 0;
    }
}

// ---- build compacted active-polyline list ----
__global__ void build_active_kernel(const void* __restrict__ maskp) {
    const int t = threadIdx.x;
    const int i = blockIdx.x * 256 + t;
    int f = 0;
    if (t < 64) {
        unsigned v = ((const unsigned*)maskp)[t];
        f = (v & 0xFFFFFF00u) ? 1 : 0;
    }
    int isbyte = __syncthreads_or(f);
    bool m = isbyte ? (((const unsigned char*)maskp)[i] != 0)
                    : (((const int*)maskp)[i] != 0);
    if (m) {
        int p = atomicAdd(&g_count, 1);
        g_active[p] = i;
    }
}

// ---- shared-memory union: main path vs PE path ----
// PE overlay: sine occupies buf[0 : 256*16); after all sine reads complete
// (hp lives in registers at that point), hp overwrites buf[0 : 512*16).
union SmemU {
    struct {
        float h1T[D1 * PP];         // 10 KB; max-exchange scratch in stage 4
        float h2T[D2 * PP];         // 20 KB
        float vec[D2];
        float pts[MPTS * 2 + 2];
        float feat[PP * 6];
    } m;
    struct {
        float buf[512 * 16];        // sine [c][r] (first half) -> hp [k][r]
    } p;
};

// ---- merged kernel: grid 17x1024 blocks. bid%17==16 -> PE block (chunk
// bid/17, 16 actives); else main polyline block (poly = bid - bid/17).
__global__ __launch_bounds__(128, 4) void map_encoder_kernel(
    const float* __restrict__ tgt,      // (B,N,21,2)
    const int* __restrict__ label,      // (B,N)
    const void* __restrict__ maskp,     // (B,N) bool or int32
    const float* __restrict__ W1, const float* __restrict__ b1,
    const float* __restrict__ g1, const float* __restrict__ be1,
    const float* __restrict__ m1, const float* __restrict__ v1,
    const float* __restrict__ W2, const float* __restrict__ b2,
    const float* __restrict__ W3,
    const float* __restrict__ g2, const float* __restrict__ be2,
    const float* __restrict__ m2, const float* __restrict__ v2,
    const float* __restrict__ W4, const float* __restrict__ b4,
    const float* __restrict__ temb,     // (16,256)
    const float* __restrict__ Wp1, const float* __restrict__ bp1,
    const float* __restrict__ Wp2, const float* __restrict__ bp2,
    const float* __restrict__ pcr,      // (6,)
    float* __restrict__ out)
{
    __shared__ __align__(16) SmemU sm;

    const int bid = blockIdx.x;
    const int t = threadIdx.x;          // 0..127
    const int q17 = bid / 17;
    float* __restrict__ pos_out = out + (size_t)BN_TOTAL * D2;

    if (bid - q17 * 17 == 16) {
        // ================= PE block: chunk q17, 16 active rows =================
        const int base = q17 * 16;
        int nb = g_count - base;
        if (nb <= 0) return;
        if (nb > 16) nb = 16;
        float* __restrict__ sine = sm.p.buf;   // [c][r], c<256
        float* __restrict__ hp   = sm.p.buf;   // [k][r], k<512 (post-overlay)

        // ---- sine: thread (r=t&15, cg=t>>4) computes channels cg*32..cg*32+31 ----
        {
            int r = t & 15, cg = t >> 4;
            int rr = (r < nb) ? r : 0;
            int poly = g_active[base + rr];
            float cvx = tgt[(size_t)poly * (MPTS * 2) + 20];
            float cvy = tgt[(size_t)poly * (MPTS * 2) + 21];
            float px = (cvx - pcr[0]) / (pcr[3] - pcr[0]);
            float py = (cvy - pcr[1]) / (pcr[4] - pcr[1]);
            float pos = (cg < 4) ? py : px;
            #pragma unroll
            for (int j = 0; j < 32; ++j) {
                int c = cg * 32 + j;
                float arg = pos * g_scale[c];
                sine[c * 16 + r] = (c & 1) ? cosf(arg) : sinf(arg);
            }
        }
        __syncthreads();

        // ---- hp = relu(sine @ Wp1 + bp1): thread t -> cols 4t..4t+3, 16 rows ----
        {
            ull a[4][8];
            float4 bb = *(const float4*)(bp1 + 4 * t);
            float bj[4] = {bb.x, bb.y, bb.z, bb.w};
            #pragma unroll
            for (int j = 0; j < 4; ++j)
                #pragma unroll
                for (int q = 0; q < 8; ++q) a[j][q] = pack2(bj[j], bj[j]);
            #pragma unroll 2
            for (int c = 0; c < D2; ++c) {
                float4 w = *(const float4*)(Wp1 + c * 512 + 4 * t);
                ull w0 = pack2(w.x, w.x), w1 = pack2(w.y, w.y);
                ull w2v = pack2(w.z, w.z), w3v = pack2(w.w, w.w);
                const ulonglong2* sv = (const ulonglong2*)(sine + c * 16);
                ulonglong2 hA = sv[0], hB = sv[1];
                a[0][0] = ffma2(hA.x, w0, a[0][0]);
                a[0][1] = ffma2(hA.y, w0, a[0][1]);
                a[0][2] = ffma2(hB.x, w0, a[0][2]);
                a[0][3] = ffma2(hB.y, w0, a[0][3]);
                a[1][0] = ffma2(hA.x, w1, a[1][0]);
                a[1][1] = ffma2(hA.y, w1, a[1][1]);
                a[1][2] = ffma2(hB.x, w1, a[1][2]);
                a[1][3] = ffma2(hB.y, w1, a[1][3]);
                a[2][0] = ffma2(hA.x, w2v, a[2][0]);
                a[2][1] = ffma2(hA.y, w2v, a[2][1]);
                a[2][2] = ffma2(hB.x, w2v, a[2][2]);
                a[2][3] = ffma2(hB.y, w2v, a[2][3]);
                a[3][0] = ffma2(hA.x, w3v, a[3][0]);
                a[3][1] = ffma2(hA.y, w3v, a[3][1]);
                a[3][2] = ffma2(hB.x, w3v, a[3][2]);
                a[3][3] = ffma2(hB.y, w3v, a[3][3]);
                ulonglong2 hC = sv[2], hD = sv[3];
                a[0][4] = ffma2(hC.x, w0, a[0][4]);
                a[0][5] = ffma2(hC.y, w0, a[0][5]);
                a[0][6] = ffma2(hD.x, w0, a[0][6]);
                a[0][7] = ffma2(hD.y, w0, a[0][7]);
                a[1][4] = ffma2(hC.x, w1, a[1][4]);
                a[1][5] = ffma2(hC.y, w1, a[1][5]);
                a[1][6] = ffma2(hD.x, w1, a[1][6]);
                a[1][7] = ffma2(hD.y, w1, a[1][7]);
                a[2][4] = ffma2(hC.x, w2v, a[2][4]);
                a[2][5] = ffma2(hC.y, w2v, a[2][5]);
                a[2][6] = ffma2(hD.x, w2v, a[2][6]);
                a[2][7] = ffma2(hD.y, w2v, a[2][7]);
                a[3][4] = ffma2(hC.x, w3v, a[3][4]);
                a[3][5] = ffma2(hC.y, w3v, a[3][5]);
                a[3][6] = ffma2(hD.x, w3v, a[3][6]);
                a[3][7] = ffma2(hD.y, w3v, a[3][7]);
            }
            __syncthreads();   // ALL sine reads complete before hp overlays buf
            #pragma unroll
            for (int j = 0; j < 4; ++j) {
                float* kcol = hp + (4 * t + j) * 16;
                #pragma unroll
                for (int q = 0; q < 8; ++q) {
                    float x, y;
                    unpack2(a[j][q], x, y);
                    *(float2*)&kcol[2 * q] =
                        make_float2(fmaxf(x, 0.f), fmaxf(y, 0.f));
                }
            }
        }
        __syncthreads();

        // ---- pe = hp @ Wp2 + bp2: thread t -> cols 2t, 2t+1, 16 rows ----
        {
            ull a0[8], a1[8];
            float2 bb = *(const float2*)(bp2 + 2 * t);
            #pragma unroll
            for (int q = 0; q < 8; ++q) {
                a0[q] = pack2(bb.x, bb.x);
                a1[q] = pack2(bb.y, bb.y);
            }
            #pragma unroll 2
            for (int k = 0; k < 512; ++k) {
                float2 w = *(const float2*)(Wp2 + k * D2 + 2 * t);
                ull w0 = pack2(w.x, w.x), w1 = pack2(w.y, w.y);
                const ulonglong2* hv = (const ulonglong2*)(hp + k * 16);
                ulonglong2 hA = hv[0], hB = hv[1];
                a0[0] = ffma2(hA.x, w0, a0[0]);
                a0[1] = ffma2(hA.y, w0, a0[1]);
                a0[2] = ffma2(hB.x, w0, a0[2]);
                a0[3] = ffma2(hB.y, w0, a0[3]);
                a1[0] = ffma2(hA.x, w1, a1[0]);
                a1[1] = ffma2(hA.y, w1, a1[1]);
                a1[2] = ffma2(hB.x, w1, a1[2]);
                a1[3] = ffma2(hB.y, w1, a1[3]);
                ulonglong2 hC = hv[2], hD = hv[3];
                a0[4] = ffma2(hC.x, w0, a0[4]);
                a0[5] = ffma2(hC.y, w0, a0[5]);
                a0[6] = ffma2(hD.x, w0, a0[6]);
                a0[7] = ffma2(hD.y, w0, a0[7]);
                a1[4] = ffma2(hC.x, w1, a1[4]);
                a1[5] = ffma2(hC.y, w1, a1[5]);
                a1[6] = ffma2(hD.x, w1, a1[6]);
                a1[7] = ffma2(hD.y, w1, a1[7]);
            }
            #pragma unroll
            for (int q = 0; q < 8; ++q) {
                float x0, y0, x1, y1;
                unpack2(a0[q], x0, y0);   // rows 2q, 2q+1 of col 2t
                unpack2(a1[q], x1, y1);   // rows 2q, 2q+1 of col 2t+1
                int r0 = 2 * q, r1 = 2 * q + 1;
                if (r0 < nb) {
                    int poly = g_active[base + r0];
                    *(float2*)&pos_out[(size_t)poly * D2 + 2 * t] =
                        make_float2(x0, x1);
                }
                if (r1 < nb) {
                    int poly = g_active[base + r1];
                    *(float2*)&pos_out[(size_t)poly * D2 + 2 * t] =
                        make_float2(y0, y1);
                }
            }
        }
        return;
    }

    // ===================== main polyline block =====================
    const int idx = bid - q17;

    // inline mask-dtype detection (uniform across grid)
    int f = 0;
    if (t < 64) {
        unsigned v = ((const unsigned*)maskp)[t];
        f = (v & 0xFFFFFF00u) ? 1 : 0;
    }
    int isbyte = __syncthreads_or(f);
    bool mask = isbyte ? (((const unsigned char*)maskp)[idx] != 0)
                       : (((const int*)maskp)[idx] != 0);

    float* __restrict__ feats_out = out;
    float* __restrict__ mask_out  = out + (size_t)2 * BN_TOTAL * D2;

    if (!mask) {
        *(float2*)&feats_out[(size_t)idx * D2 + 2 * t] = make_float2(0.f, 0.f);
        *(float2*)&pos_out[(size_t)idx * D2 + 2 * t]   = make_float2(0.f, 0.f);
        if (t == 0) mask_out[idx] = 1.0f;
        return;
    }
    if (t == 0) mask_out[idx] = 0.0f;

    // ---- load points ----
    const float* ppin = tgt + (size_t)idx * MPTS * 2;
    if (t < MPTS * 2) sm.m.pts[t] = ppin[t];
    __syncthreads();

    // ---- feature construction ----
    if (t < PP) {
        int p = t;
        float cx = sm.m.pts[10 * 2], cy = sm.m.pts[10 * 2 + 1];
        float x0 = sm.m.pts[2 * p],     y0 = sm.m.pts[2 * p + 1];
        float x1 = sm.m.pts[2 * p + 2], y1 = sm.m.pts[2 * p + 3];
        float pvx = x1 - x0, pvy = y1 - y0;
        float vn = sqrtf(pvx * pvx + pvy * pvy) + 1.0f + 1e-6f;
        float inv = 1.0f / vn;
        sm.m.feat[p * 6 + 0] = x0 - cx;
        sm.m.feat[p * 6 + 1] = y0 - cy;
        sm.m.feat[p * 6 + 2] = pvx;
        sm.m.feat[p * 6 + 3] = pvy;
        sm.m.feat[p * 6 + 4] = pvx * inv;
        sm.m.feat[p * 6 + 5] = pvy * inv;
    }
    __syncthreads();

    // ---- stage 1: feat(20x6)@W1+b1 -> BN1 -> relu -> h1T ----
    {
        int d = t;
        float w0 = W1[0 * D1 + d], w1 = W1[1 * D1 + d], w2 = W1[2 * D1 + d];
        float w3 = W1[3 * D1 + d], w4 = W1[4 * D1 + d], w5 = W1[5 * D1 + d];
        float s  = g1[d] * rsqrtf(v1[d] + 1e-5f);
        float sh = be1[d] - m1[d] * s + b1[d] * s;
        #pragma unroll
        for (int p = 0; p < PP; ++p) {
            const float* fv = &sm.m.feat[p * 6];
            float lin = fv[0] * w0 + fv[1] * w1 + fv[2] * w2
                      + fv[3] * w3 + fv[4] * w4 + fv[5] * w5;
            sm.m.h1T[d * PP + p] = fmaxf(lin * s + sh, 0.0f);
        }
    }
    __syncthreads();

    // ---- FUSED stage2 (h1@W2 -> pooled) + stage3 h-term (h1@W23) ----
    ull a3c0[10], a3c1[10];
    {
        ull a2c0[10], a2c1[10];
        #pragma unroll
        for (int q = 0; q < 10; ++q) {
            a2c0[q] = 0ull; a2c1[q] = 0ull; a3c0[q] = 0ull; a3c1[q] = 0ull;
        }
        #pragma unroll 2
        for (int c = 0; c < D1; ++c) {
            float2 w2v = *(const float2*)(W2 + c * D2 + 2 * t);
            float2 w3v = *(const float2*)(g_W23 + c * D2 + 2 * t);
            ull w20 = pack2(w2v.x, w2v.x), w21 = pack2(w2v.y, w2v.y);
            ull w30 = pack2(w3v.x, w3v.x), w31 = pack2(w3v.y, w3v.y);
            const ulonglong2* hv = (const ulonglong2*)(sm.m.h1T + c * PP);
            #pragma unroll
            for (int q = 0; q < 5; ++q) {
                ulonglong2 h = hv[q];
                a2c0[2 * q]     = ffma2(h.x, w20, a2c0[2 * q]);
                a2c0[2 * q + 1] = ffma2(h.y, w20, a2c0[2 * q + 1]);
                a2c1[2 * q]     = ffma2(h.x, w21, a2c1[2 * q]);
                a2c1[2 * q + 1] = ffma2(h.y, w21, a2c1[2 * q + 1]);
                a3c0[2 * q]     = ffma2(h.x, w30, a3c0[2 * q]);
                a3c0[2 * q + 1] = ffma2(h.y, w30, a3c0[2 * q + 1]);
                a3c1[2 * q]     = ffma2(h.x, w31, a3c1[2 * q]);
                a3c1[2 * q + 1] = ffma2(h.y, w31, a3c1[2 * q + 1]);
            }
        }
        float2 bb = *(const float2*)(b2 + 2 * t);
        float mx0 = -FLT_MAX, mx1 = -FLT_MAX;
        #pragma unroll
        for (int q = 0; q < 10; ++q) {
            float a, b;
            unpack2(a2c0[q], a, b); mx0 = fmaxf(mx0, fmaxf(a, b));
            unpack2(a2c1[q], a, b); mx1 = fmaxf(mx1, fmaxf(a, b));
        }
        *(float2*)&sm.m.vec[2 * t] = make_float2(mx0 + bb.x, mx1 + bb.y);
    }
    __syncthreads();

    // ---- stage 3 epilogue: base = pooled@W3[256:] + bc; BN2+relu -> h2T ----
    {
        ull base = 0ull;
        #pragma unroll 4
        for (int c = 0; c < D2; ++c) {
            ull wb = *(const ull*)(W3 + (size_t)(D2 + c) * D2 + 2 * t);
            float pc = sm.m.vec[c];
            base = ffma2(wb, pack2(pc, pc), base);
        }
        float bx, by;
        unpack2(base, bx, by);
        float2 bcv = *(const float2*)(g_bc + 2 * t);
        bx += bcv.x; by += bcv.y;

        float2 gg = *(const float2*)(g2  + 2 * t);
        float2 vv = *(const float2*)(v2  + 2 * t);
        float2 mm = *(const float2*)(m2  + 2 * t);
        float2 ee = *(const float2*)(be2 + 2 * t);
        float s0 = gg.x * rsqrtf(vv.x + 1e-5f);
        float s1 = gg.y * rsqrtf(vv.y + 1e-5f);
        float sh0 = ee.x - mm.x * s0;
        float sh1 = ee.y - mm.y * s1;
        float* r0 = sm.m.h2T + (2 * t) * PP;
        float* r1 = sm.m.h2T + (2 * t + 1) * PP;
        #pragma unroll
        for (int q = 0; q < 10; ++q) {
            float a, b;
            unpack2(a3c0[q], a, b);
            *(float2*)&r0[2 * q] =
                make_float2(fmaxf((a + bx) * s0 + sh0, 0.0f),
                            fmaxf((b + bx) * s0 + sh0, 0.0f));
            unpack2(a3c1[q], a, b);
            *(float2*)&r1[2 * q] =
                make_float2(fmaxf((a + by) * s1 + sh1, 0.0f),
                            fmaxf((b + by) * s1 + sh1, 0.0f));
        }
    }
    __syncthreads();

    // ---- stage 4: h2(20x256)@W4+b4 -> max_p -> +type_emb -> out ----
    // 4 cols x 10 points per thread (cq = t&63, ph4 = t>>6): per c-iter
    // 1 LDG.128 + 5 LDS.64 feed 20 FFMA2 (~9 wf/c vs 12 before). c stays
    // whole, so only per-column point-MAXES are exchanged (float4 through
    // dead h1T scratch), not accumulators. Arithmetic bit-identical.
    {
        const int cq = t & 63;
        const int ph4 = t >> 6;
        ull acc[4][5];
        #pragma unroll
        for (int j = 0; j < 4; ++j)
            #pragma unroll
            for (int q = 0; q < 5; ++q) acc[j][q] = 0ull;
        #pragma unroll 2
        for (int c = 0; c < D2; ++c) {
            float4 w = *(const float4*)(W4 + c * D2 + 4 * cq);
            ull w0 = pack2(w.x, w.x), w1 = pack2(w.y, w.y);
            ull w2v = pack2(w.z, w.z), w3v = pack2(w.w, w.w);
            const ull* hv = (const ull*)(sm.m.h2T + c * PP + ph4 * 10);
            #pragma unroll
            for (int q = 0; q < 5; ++q) {
                ull h = hv[q];
                acc[0][q] = ffma2(h, w0, acc[0][q]);
                acc[1][q] = ffma2(h, w1, acc[1][q]);
                acc[2][q] = ffma2(h, w2v, acc[2][q]);
                acc[3][q] = ffma2(h, w3v, acc[3][q]);
            }
        }
        float mx[4];
        #pragma unroll
        for (int j = 0; j < 4; ++j) {
            float m = -FLT_MAX;
            #pragma unroll
            for (int q = 0; q < 5; ++q) {
                float a, b;
                unpack2(acc[j][q], a, b);
                m = fmaxf(m, fmaxf(a, b));
            }
            mx[j] = m;
        }
        // h1T dead since the fused stage-2/3 loop -> max-exchange scratch
        *(float4*)&sm.m.h1T[cq * 8 + ph4 * 4] =
            make_float4(mx[0], mx[1], mx[2], mx[3]);
        __syncthreads();
        if (t < 64) {
            float4 mA = *(const float4*)&sm.m.h1T[t * 8];
            float4 mB = *(const float4*)&sm.m.h1T[t * 8 + 4];
            float4 bb = *(const float4*)(b4 + 4 * t);
            int lb = label[idx];
            float4 tv = *(const float4*)(temb + (size_t)lb * D2 + 4 * t);
            *(float4*)&feats_out[(size_t)idx * D2 + 4 * t] =
                make_float4(fmaxf(mA.x, mB.x) + bb.x + tv.x,
                            fmaxf(mA.y, mB.y) + bb.y + tv.y,
                            fmaxf(mA.z, mB.z) + bb.z + tv.z,
                            fmaxf(mA.w, mB.w) + bb.w + tv.w);
        }
    }
}

extern "C" void kernel_launch(void* const* d_in, const int* in_sizes, int n_in,
                              void* d_out, int out_size) {
    (void)in_sizes; (void)n_in; (void)out_size;

    const float* tgt   = (const float*)d_in[0];
    const int*   label = (const int*)d_in[1];
    const void*  maskp = d_in[2];
    const float* W1  = (const float*)d_in[3];
    const float* b1  = (const float*)d_in[4];
    const float* g1  = (const float*)d_in[5];
    const float* be1 = (const float*)d_in[6];
    const float* m1  = (const float*)d_in[7];
    const float* v1  = (const float*)d_in[8];
    const float* W2  = (const float*)d_in[9];
    const float* b2  = (const float*)d_in[10];
    const float* W3  = (const float*)d_in[11];
    const float* b3  = (const float*)d_in[12];
    const float* g2  = (const float*)d_in[13];
    const float* be2 = (const float*)d_in[14];
    const float* m2  = (const float*)d_in[15];
    const float* v2  = (const float*)d_in[16];
    const float* W4  = (const float*)d_in[17];
    const float* b4  = (const float*)d_in[18];
    const float* temb = (const float*)d_in[19];
    const float* Wp1 = (const float*)d_in[20];
    const float* bp1 = (const float*)d_in[21];
    const float* Wp2 = (const float*)d_in[22];
    const float* bp2 = (const float*)d_in[23];
    const float* pcr = (const float*)d_in[24];

    precompute_w23_kernel<<<129, 256>>>(W2, W3, b2, b3);
    build_active_kernel<<<BN_TOTAL / 256, 256>>>(maskp);
    map_encoder_kernel<<<17 * (BN_TOTAL / 16), 128>>>(
        tgt, label, maskp,
        W1, b1, g1, be1, m1, v1,
        W2, b2, W3, g2, be2, m2, v2,
        W4, b4, temb, Wp1, bp1, Wp2, bp2, pcr,
        (float*)d_out);
}

// round 15
// speedup vs baseline: 1.0508x; 1.0508x over previous
#include <cuda_runtime.h>
#include <float.h>

// Problem constants (fixed by the reference: B=16, N=1024, M=21, D=256, V=16)
#define BN_TOTAL (16 * 1024)
#define MPTS 21
#define PP 20      // M-1 points per polyline
#define D1 128
#define D2 256

typedef unsigned long long ull;

// ---- packed f32x2 helpers (Blackwell FFMA2) ----
__device__ __forceinline__ ull pack2(float x, float y) {
    ull r;
    asm("mov.b64 %0, {%1, %2};" : "=l"(r) : "f"(x), "f"(y));
    return r;
}
__device__ __forceinline__ void unpack2(ull v, float& x, float& y) {
    asm("mov.b64 {%0, %1}, %2;" : "=f"(x), "=f"(y) : "l"(v));
}
__device__ __forceinline__ ull ffma2(ull a, ull b, ull c) {
    ull d;
    asm("fma.rn.f32x2 %0, %1, %2, %3;" : "=l"(d) : "l"(a), "l"(b), "l"(c));
    return d;
}
__device__ __forceinline__ ull addf2(ull a, ull b) {
    ull d;
    asm("add.rn.f32x2 %0, %1, %2;" : "=l"(d) : "l"(a), "l"(b));
    return d;
}

__device__ float g_W23[D1 * D2];   // W2 @ W3[:256]  (128x256)
__device__ float g_bc[D2];         // b2 @ W3[:256] + b3
__device__ float g_scale[D2];      // sine arg multiplier per channel
__device__ int   g_count;
__device__ int   g_active[BN_TOTAL];

// ---- precompute: W23, bc, sine scale table, zero active-count ----
// Grid 129: blocks 0..127 -> one W23 row each (8-way-MLP inner loop);
// block 128 -> bc + scale table + count reset.
__global__ void precompute_w23_kernel(const float* __restrict__ W2,
                                      const float* __restrict__ W3,
                                      const float* __restrict__ b2,
                                      const float* __restrict__ b3) {
    __shared__ float row[D2];
    const int blk = blockIdx.x;
    const int d = threadIdx.x;   // 0..255
    if (blk < 128) {
        row[d] = W2[blk * D2 + d];     // W2 row `blk`
        __syncthreads();
        float acc[8];
        #pragma unroll
        for (int j = 0; j < 8; ++j) acc[j] = 0.f;
        #pragma unroll 1
        for (int k0 = 0; k0 < D2; k0 += 8) {
            #pragma unroll
            for (int j = 0; j < 8; ++j)
                acc[j] = fmaf(row[k0 + j], W3[(k0 + j) * D2 + d], acc[j]);
        }
        float s = ((acc[0] + acc[1]) + (acc[2] + acc[3]))
                + ((acc[4] + acc[5]) + (acc[6] + acc[7]));
        g_W23[blk * D2 + d] = s;
    } else {
        row[d] = b2[d];
        __syncthreads();
        float acc[8];
        #pragma unroll
        for (int j = 0; j < 8; ++j) acc[j] = 0.f;
        #pragma unroll 1
        for (int k0 = 0; k0 < D2; k0 += 8) {
            #pragma unroll
            for (int j = 0; j < 8; ++j)
                acc[j] = fmaf(row[k0 + j], W3[(k0 + j) * D2 + d], acc[j]);
        }
        float s = ((acc[0] + acc[1]) + (acc[2] + acc[3]))
                + ((acc[4] + acc[5]) + (acc[6] + acc[7]));
        g_bc[d] = s + b3[d];
        int i = (d & 127) >> 1;
        float freq = powf(10000.0f, (float)i * (1.0f / 64.0f));
        g_scale[d] = 6.283185307179586f / freq;
        if (d == 0) g_count = 0;
    }
}

// ---- build compacted active-polyline list ----
__global__ void build_active_kernel(const void* __restrict__ maskp) {
    const int t = threadIdx.x;
    const int i = blockIdx.x * 256 + t;
    int f = 0;
    if (t < 64) {
        unsigned v = ((const unsigned*)maskp)[t];
        f = (v & 0xFFFFFF00u) ? 1 : 0;
    }
    int isbyte = __syncthreads_or(f);
    bool m = isbyte ? (((const unsigned char*)maskp)[i] != 0)
                    : (((const int*)maskp)[i] != 0);
    if (m) {
        int p = atomicAdd(&g_count, 1);
        g_active[p] = i;
    }
}

// ---- shared-memory union: main path vs PE path ----
// PE overlay: sine occupies buf[0 : 256*16); after all sine reads complete
// (hp lives in registers at that point), hp overwrites buf[0 : 512*16).
// PE footprint = 32 KB <= main footprint (~32.4 KB) -> union 32.4 KB.
union SmemU {
    struct {
        float h1T[D1 * PP];         // 10 KB
        float h2T[D2 * PP];         // 20 KB
        float vec[D2];
        float pts[MPTS * 2 + 2];
        float feat[PP * 6];
    } m;
    struct {
        float buf[512 * 16];        // sine [c][r] (first half) -> hp [k][r]
    } p;
};

// ---- merged kernel: grid 17x1024 blocks. bid%17==16 -> PE block (chunk
// bid/17, 16 actives); else main polyline block (poly = bid - bid/17).
__global__ __launch_bounds__(128, 4) void map_encoder_kernel(
    const float* __restrict__ tgt,      // (B,N,21,2)
    const int* __restrict__ label,      // (B,N)
    const void* __restrict__ maskp,     // (B,N) bool or int32
    const float* __restrict__ W1, const float* __restrict__ b1,
    const float* __restrict__ g1, const float* __restrict__ be1,
    const float* __restrict__ m1, const float* __restrict__ v1,
    const float* __restrict__ W2, const float* __restrict__ b2,
    const float* __restrict__ W3,
    const float* __restrict__ g2, const float* __restrict__ be2,
    const float* __restrict__ m2, const float* __restrict__ v2,
    const float* __restrict__ W4, const float* __restrict__ b4,
    const float* __restrict__ temb,     // (16,256)
    const float* __restrict__ Wp1, const float* __restrict__ bp1,
    const float* __restrict__ Wp2, const float* __restrict__ bp2,
    const float* __restrict__ pcr,      // (6,)
    float* __restrict__ out)
{
    __shared__ __align__(16) SmemU sm;

    const int bid = blockIdx.x;
    const int t = threadIdx.x;          // 0..127
    const int q17 = bid / 17;
    float* __restrict__ pos_out = out + (size_t)BN_TOTAL * D2;

    if (bid - q17 * 17 == 16) {
        // ================= PE block: chunk q17, 16 active rows =================
        const int base = q17 * 16;
        int nb = g_count - base;
        if (nb <= 0) return;
        if (nb > 16) nb = 16;
        float* __restrict__ sine = sm.p.buf;   // [c][r], c<256
        float* __restrict__ hp   = sm.p.buf;   // [k][r], k<512 (post-overlay)

        // ---- sine: thread (r=t&15, cg=t>>4) computes channels cg*32..cg*32+31 ----
        {
            int r = t & 15, cg = t >> 4;
            int rr = (r < nb) ? r : 0;
            int poly = g_active[base + rr];
            float cvx = tgt[(size_t)poly * (MPTS * 2) + 20];
            float cvy = tgt[(size_t)poly * (MPTS * 2) + 21];
            float px = (cvx - pcr[0]) / (pcr[3] - pcr[0]);
            float py = (cvy - pcr[1]) / (pcr[4] - pcr[1]);
            float pos = (cg < 4) ? py : px;
            #pragma unroll
            for (int j = 0; j < 32; ++j) {
                int c = cg * 32 + j;
                float arg = pos * g_scale[c];
                sine[c * 16 + r] = (c & 1) ? cosf(arg) : sinf(arg);
            }
        }
        __syncthreads();

        // ---- hp = relu(sine @ Wp1 + bp1): thread t -> cols 4t..4t+3, 16 rows.
        // All of hp (128 thr x 64 vals) is register-resident until the store. ----
        {
            ull a[4][8];
            float4 bb = *(const float4*)(bp1 + 4 * t);
            float bj[4] = {bb.x, bb.y, bb.z, bb.w};
            #pragma unroll
            for (int j = 0; j < 4; ++j)
                #pragma unroll
                for (int q = 0; q < 8; ++q) a[j][q] = pack2(bj[j], bj[j]);
            #pragma unroll 2
            for (int c = 0; c < D2; ++c) {
                float4 w = *(const float4*)(Wp1 + c * 512 + 4 * t);
                ull w0 = pack2(w.x, w.x), w1 = pack2(w.y, w.y);
                ull w2v = pack2(w.z, w.z), w3v = pack2(w.w, w.w);
                const ulonglong2* sv = (const ulonglong2*)(sine + c * 16);
                ulonglong2 hA = sv[0], hB = sv[1];
                a[0][0] = ffma2(hA.x, w0, a[0][0]);
                a[0][1] = ffma2(hA.y, w0, a[0][1]);
                a[0][2] = ffma2(hB.x, w0, a[0][2]);
                a[0][3] = ffma2(hB.y, w0, a[0][3]);
                a[1][0] = ffma2(hA.x, w1, a[1][0]);
                a[1][1] = ffma2(hA.y, w1, a[1][1]);
                a[1][2] = ffma2(hB.x, w1, a[1][2]);
                a[1][3] = ffma2(hB.y, w1, a[1][3]);
                a[2][0] = ffma2(hA.x, w2v, a[2][0]);
                a[2][1] = ffma2(hA.y, w2v, a[2][1]);
                a[2][2] = ffma2(hB.x, w2v, a[2][2]);
                a[2][3] = ffma2(hB.y, w2v, a[2][3]);
                a[3][0] = ffma2(hA.x, w3v, a[3][0]);
                a[3][1] = ffma2(hA.y, w3v, a[3][1]);
                a[3][2] = ffma2(hB.x, w3v, a[3][2]);
                a[3][3] = ffma2(hB.y, w3v, a[3][3]);
                ulonglong2 hC = sv[2], hD = sv[3];
                a[0][4] = ffma2(hC.x, w0, a[0][4]);
                a[0][5] = ffma2(hC.y, w0, a[0][5]);
                a[0][6] = ffma2(hD.x, w0, a[0][6]);
                a[0][7] = ffma2(hD.y, w0, a[0][7]);
                a[1][4] = ffma2(hC.x, w1, a[1][4]);
                a[1][5] = ffma2(hC.y, w1, a[1][5]);
                a[1][6] = ffma2(hD.x, w1, a[1][6]);
                a[1][7] = ffma2(hD.y, w1, a[1][7]);
                a[2][4] = ffma2(hC.x, w2v, a[2][4]);
                a[2][5] = ffma2(hC.y, w2v, a[2][5]);
                a[2][6] = ffma2(hD.x, w2v, a[2][6]);
                a[2][7] = ffma2(hD.y, w2v, a[2][7]);
                a[3][4] = ffma2(hC.x, w3v, a[3][4]);
                a[3][5] = ffma2(hC.y, w3v, a[3][5]);
                a[3][6] = ffma2(hD.x, w3v, a[3][6]);
                a[3][7] = ffma2(hD.y, w3v, a[3][7]);
            }
            __syncthreads();   // ALL sine reads complete before hp overlays buf
            #pragma unroll
            for (int j = 0; j < 4; ++j) {
                float* kcol = hp + (4 * t + j) * 16;
                #pragma unroll
                for (int q = 0; q < 8; ++q) {
                    float x, y;
                    unpack2(a[j][q], x, y);
                    *(float2*)&kcol[2 * q] =
                        make_float2(fmaxf(x, 0.f), fmaxf(y, 0.f));
                }
            }
        }
        __syncthreads();

        // ---- pe = hp @ Wp2 + bp2: thread t -> cols 2t, 2t+1, 16 rows ----
        {
            ull a0[8], a1[8];
            float2 bb = *(const float2*)(bp2 + 2 * t);
            #pragma unroll
            for (int q = 0; q < 8; ++q) {
                a0[q] = pack2(bb.x, bb.x);
                a1[q] = pack2(bb.y, bb.y);
            }
            #pragma unroll 2
            for (int k = 0; k < 512; ++k) {
                float2 w = *(const float2*)(Wp2 + k * D2 + 2 * t);
                ull w0 = pack2(w.x, w.x), w1 = pack2(w.y, w.y);
                const ulonglong2* hv = (const ulonglong2*)(hp + k * 16);
                ulonglong2 hA = hv[0], hB = hv[1];
                a0[0] = ffma2(hA.x, w0, a0[0]);
                a0[1] = ffma2(hA.y, w0, a0[1]);
                a0[2] = ffma2(hB.x, w0, a0[2]);
                a0[3] = ffma2(hB.y, w0, a0[3]);
                a1[0] = ffma2(hA.x, w1, a1[0]);
                a1[1] = ffma2(hA.y, w1, a1[1]);
                a1[2] = ffma2(hB.x, w1, a1[2]);
                a1[3] = ffma2(hB.y, w1, a1[3]);
                ulonglong2 hC = hv[2], hD = hv[3];
                a0[4] = ffma2(hC.x, w0, a0[4]);
                a0[5] = ffma2(hC.y, w0, a0[5]);
                a0[6] = ffma2(hD.x, w0, a0[6]);
                a0[7] = ffma2(hD.y, w0, a0[7]);
                a1[4] = ffma2(hC.x, w1, a1[4]);
                a1[5] = ffma2(hC.y, w1, a1[5]);
                a1[6] = ffma2(hD.x, w1, a1[6]);
                a1[7] = ffma2(hD.y, w1, a1[7]);
            }
            #pragma unroll
            for (int q = 0; q < 8; ++q) {
                float x0, y0, x1, y1;
                unpack2(a0[q], x0, y0);   // rows 2q, 2q+1 of col 2t
                unpack2(a1[q], x1, y1);   // rows 2q, 2q+1 of col 2t+1
                int r0 = 2 * q, r1 = 2 * q + 1;
                if (r0 < nb) {
                    int poly = g_active[base + r0];
                    *(float2*)&pos_out[(size_t)poly * D2 + 2 * t] =
                        make_float2(x0, x1);
                }
                if (r1 < nb) {
                    int poly = g_active[base + r1];
                    *(float2*)&pos_out[(size_t)poly * D2 + 2 * t] =
                        make_float2(y0, y1);
                }
            }
        }
        return;
    }

    // ===================== main polyline block =====================
    const int idx = bid - q17;

    // inline mask-dtype detection (uniform across grid)
    int f = 0;
    if (t < 64) {
        unsigned v = ((const unsigned*)maskp)[t];
        f = (v & 0xFFFFFF00u) ? 1 : 0;
    }
    int isbyte = __syncthreads_or(f);
    bool mask = isbyte ? (((const unsigned char*)maskp)[idx] != 0)
                       : (((const int*)maskp)[idx] != 0);

    float* __restrict__ feats_out = out;
    float* __restrict__ mask_out  = out + (size_t)2 * BN_TOTAL * D2;

    if (!mask) {
        *(float2*)&feats_out[(size_t)idx * D2 + 2 * t] = make_float2(0.f, 0.f);
        *(float2*)&pos_out[(size_t)idx * D2 + 2 * t]   = make_float2(0.f, 0.f);
        if (t == 0) mask_out[idx] = 1.0f;
        return;
    }
    if (t == 0) mask_out[idx] = 0.0f;

    // ---- load points ----
    const float* ppin = tgt + (size_t)idx * MPTS * 2;
    if (t < MPTS * 2) sm.m.pts[t] = ppin[t];
    __syncthreads();

    // ---- feature construction ----
    if (t < PP) {
        int p = t;
        float cx = sm.m.pts[10 * 2], cy = sm.m.pts[10 * 2 + 1];
        float x0 = sm.m.pts[2 * p],     y0 = sm.m.pts[2 * p + 1];
        float x1 = sm.m.pts[2 * p + 2], y1 = sm.m.pts[2 * p + 3];
        float pvx = x1 - x0, pvy = y1 - y0;
        float vn = sqrtf(pvx * pvx + pvy * pvy) + 1.0f + 1e-6f;
        float inv = 1.0f / vn;
        sm.m.feat[p * 6 + 0] = x0 - cx;
        sm.m.feat[p * 6 + 1] = y0 - cy;
        sm.m.feat[p * 6 + 2] = pvx;
        sm.m.feat[p * 6 + 3] = pvy;
        sm.m.feat[p * 6 + 4] = pvx * inv;
        sm.m.feat[p * 6 + 5] = pvy * inv;
    }
    __syncthreads();

    // ---- stage 1: feat(20x6)@W1+b1 -> BN1 -> relu -> h1T ----
    {
        int d = t;
        float w0 = W1[0 * D1 + d], w1 = W1[1 * D1 + d], w2 = W1[2 * D1 + d];
        float w3 = W1[3 * D1 + d], w4 = W1[4 * D1 + d], w5 = W1[5 * D1 + d];
        float s  = g1[d] * rsqrtf(v1[d] + 1e-5f);
        float sh = be1[d] - m1[d] * s + b1[d] * s;
        #pragma unroll
        for (int p = 0; p < PP; ++p) {
            const float* fv = &sm.m.feat[p * 6];
            float lin = fv[0] * w0 + fv[1] * w1 + fv[2] * w2
                      + fv[3] * w3 + fv[4] * w4 + fv[5] * w5;
            sm.m.h1T[d * PP + p] = fmaxf(lin * s + sh, 0.0f);
        }
    }
    __syncthreads();

    // ---- FUSED stage2 (h1@W2 -> pooled) + stage3 h-term (h1@W23) ----
    ull a3c0[10], a3c1[10];
    {
        ull a2c0[10], a2c1[10];
        #pragma unroll
        for (int q = 0; q < 10; ++q) {
            a2c0[q] = 0ull; a2c1[q] = 0ull; a3c0[q] = 0ull; a3c1[q] = 0ull;
        }
        #pragma unroll 2
        for (int c = 0; c < D1; ++c) {
            float2 w2v = *(const float2*)(W2 + c * D2 + 2 * t);
            float2 w3v = *(const float2*)(g_W23 + c * D2 + 2 * t);
            ull w20 = pack2(w2v.x, w2v.x), w21 = pack2(w2v.y, w2v.y);
            ull w30 = pack2(w3v.x, w3v.x), w31 = pack2(w3v.y, w3v.y);
            const ulonglong2* hv = (const ulonglong2*)(sm.m.h1T + c * PP);
            #pragma unroll
            for (int q = 0; q < 5; ++q) {
                ulonglong2 h = hv[q];
                a2c0[2 * q]     = ffma2(h.x, w20, a2c0[2 * q]);
                a2c0[2 * q + 1] = ffma2(h.y, w20, a2c0[2 * q + 1]);
                a2c1[2 * q]     = ffma2(h.x, w21, a2c1[2 * q]);
                a2c1[2 * q + 1] = ffma2(h.y, w21, a2c1[2 * q + 1]);
                a3c0[2 * q]     = ffma2(h.x, w30, a3c0[2 * q]);
                a3c0[2 * q + 1] = ffma2(h.y, w30, a3c0[2 * q + 1]);
                a3c1[2 * q]     = ffma2(h.x, w31, a3c1[2 * q]);
                a3c1[2 * q + 1] = ffma2(h.y, w31, a3c1[2 * q + 1]);
            }
        }
        float2 bb = *(const float2*)(b2 + 2 * t);
        float mx0 = -FLT_MAX, mx1 = -FLT_MAX;
        #pragma unroll
        for (int q = 0; q < 10; ++q) {
            float a, b;
            unpack2(a2c0[q], a, b); mx0 = fmaxf(mx0, fmaxf(a, b));
            unpack2(a2c1[q], a, b); mx1 = fmaxf(mx1, fmaxf(a, b));
        }
        *(float2*)&sm.m.vec[2 * t] = make_float2(mx0 + bb.x, mx1 + bb.y);
    }
    __syncthreads();

    // ---- stage 3 epilogue: base = pooled@W3[256:] + bc; BN2+relu -> h2T ----
    {
        // 4 independent accumulator chains (was 1: a 256-deep FFMA2 RAW chain)
        ull b0 = 0ull, b1v = 0ull, b2v = 0ull, b3v = 0ull;
        #pragma unroll 1
        for (int c = 0; c < D2; c += 4) {
            float p0 = sm.m.vec[c],     p1 = sm.m.vec[c + 1];
            float p2 = sm.m.vec[c + 2], p3 = sm.m.vec[c + 3];
            b0  = ffma2(*(const ull*)(W3 + (size_t)(D2 + c) * D2 + 2 * t),
                        pack2(p0, p0), b0);
            b1v = ffma2(*(const ull*)(W3 + (size_t)(D2 + c + 1) * D2 + 2 * t),
                        pack2(p1, p1), b1v);
            b2v = ffma2(*(const ull*)(W3 + (size_t)(D2 + c + 2) * D2 + 2 * t),
                        pack2(p2, p2), b2v);
            b3v = ffma2(*(const ull*)(W3 + (size_t)(D2 + c + 3) * D2 + 2 * t),
                        pack2(p3, p3), b3v);
        }
        ull base = addf2(addf2(b0, b1v), addf2(b2v, b3v));
        float bx, by;
        unpack2(base, bx, by);
        float2 bcv = *(const float2*)(g_bc + 2 * t);
        bx += bcv.x; by += bcv.y;

        float2 gg = *(const float2*)(g2  + 2 * t);
        float2 vv = *(const float2*)(v2  + 2 * t);
        float2 mm = *(const float2*)(m2  + 2 * t);
        float2 ee = *(const float2*)(be2 + 2 * t);
        float s0 = gg.x * rsqrtf(vv.x + 1e-5f);
        float s1 = gg.y * rsqrtf(vv.y + 1e-5f);
        float sh0 = ee.x - mm.x * s0;
        float sh1 = ee.y - mm.y * s1;
        float* r0 = sm.m.h2T + (2 * t) * PP;
        float* r1 = sm.m.h2T + (2 * t + 1) * PP;
        #pragma unroll
        for (int q = 0; q < 10; ++q) {
            float a, b;
            unpack2(a3c0[q], a, b);
            *(float2*)&r0[2 * q] =
                make_float2(fmaxf((a + bx) * s0 + sh0, 0.0f),
                            fmaxf((b + bx) * s0 + sh0, 0.0f));
            unpack2(a3c1[q], a, b);
            *(float2*)&r1[2 * q] =
                make_float2(fmaxf((a + by) * s1 + sh1, 0.0f),
                            fmaxf((b + by) * s1 + sh1, 0.0f));
        }
    }
    __syncthreads();

    // ---- stage 4: h2(20x256)@W4+b4 -> max_p -> +type_emb -> out ----
    // (2 cols x 20 pts per thread: the measured-best geometry)
    {
        ull acc0[10], acc1[10];
        #pragma unroll
        for (int q = 0; q < 10; ++q) { acc0[q] = 0ull; acc1[q] = 0ull; }
        #pragma unroll 2
        for (int c = 0; c < D2; ++c) {
            float2 w = *(const float2*)(W4 + c * D2 + 2 * t);
            ull w0 = pack2(w.x, w.x);
            ull w1 = pack2(w.y, w.y);
            const ulonglong2* hv = (const ulonglong2*)(sm.m.h2T + c * PP);
            #pragma unroll
            for (int q = 0; q < 5; ++q) {
                ulonglong2 h = hv[q];
                acc0[2 * q]     = ffma2(h.x, w0, acc0[2 * q]);
                acc0[2 * q + 1] = ffma2(h.y, w0, acc0[2 * q + 1]);
                acc1[2 * q]     = ffma2(h.x, w1, acc1[2 * q]);
                acc1[2 * q + 1] = ffma2(h.y, w1, acc1[2 * q + 1]);
            }
        }
        float2 bb = *(const float2*)(b4 + 2 * t);
        float mx0 = -FLT_MAX, mx1 = -FLT_MAX;
        #pragma unroll
        for (int q = 0; q < 10; ++q) {
            float a, b;
            unpack2(acc0[q], a, b); mx0 = fmaxf(mx0, fmaxf(a, b));
            unpack2(acc1[q], a, b); mx1 = fmaxf(mx1, fmaxf(a, b));
        }
        int lb = label[idx];
        float2 tv = *(const float2*)(temb + (size_t)lb * D2 + 2 * t);
        *(float2*)&feats_out[(size_t)idx * D2 + 2 * t] =
            make_float2(mx0 + bb.x + tv.x, mx1 + bb.y + tv.y);
    }
}

extern "C" void kernel_launch(void* const* d_in, const int* in_sizes, int n_in,
                              void* d_out, int out_size) {
    (void)in_sizes; (void)n_in; (void)out_size;

    const float* tgt   = (const float*)d_in[0];
    const int*   label = (const int*)d_in[1];
    const void*  maskp = d_in[2];
    const float* W1  = (const float*)d_in[3];
    const float* b1  = (const float*)d_in[4];
    const float* g1  = (const float*)d_in[5];
    const float* be1 = (const float*)d_in[6];
    const float* m1  = (const float*)d_in[7];
    const float* v1  = (const float*)d_in[8];
    const float* W2  = (const float*)d_in[9];
    const float* b2  = (const float*)d_in[10];
    const float* W3  = (const float*)d_in[11];
    const float* b3  = (const float*)d_in[12];
    const float* g2  = (const float*)d_in[13];
    const float* be2 = (const float*)d_in[14];
    const float* m2  = (const float*)d_in[15];
    const float* v2  = (const float*)d_in[16];
    const float* W4  = (const float*)d_in[17];
    const float* b4  = (const float*)d_in[18];
    const float* temb = (const float*)d_in[19];
    const float* Wp1 = (const float*)d_in[20];
    const float* bp1 = (const float*)d_in[21];
    const float* Wp2 = (const float*)d_in[22];
    const float* bp2 = (const float*)d_in[23];
    const float* pcr = (const float*)d_in[24];

    precompute_w23_kernel<<<129, 256>>>(W2, W3, b2, b3);
    build_active_kernel<<<BN_TOTAL / 256, 256>>>(maskp);
    map_encoder_kernel<<<17 * (BN_TOTAL / 16), 128>>>(
        tgt, label, maskp,
        W1, b1, g1, be1, m1, v1,
        W2, b2, W3, g2, be2, m2, v2,
        W4, b4, temb, Wp1, bp1, Wp2, bp2, pcr,
        (float*)d_out);
}